// round 5
// baseline (speedup 1.0000x reference)
#include <cuda_runtime.h>
#include <math.h>

// Problem constants
#define Bn   4
#define Nn   8192
#define Cc   384
#define Hh   12
#define Dd   2
#define Kk   256
#define Mm   32          // members per cluster
#define CHh  32          // channels per head
#define TOT  (Bn * Nn)   // 32768 rows
#define Zz   (Bn * Kk)   // 1024 clusters
#define TQ   128         // queries per attention CTA

// ---------------------------------------------------------------------------
// Scratch (device globals: no allocation allowed in kernel_launch)
// ---------------------------------------------------------------------------
__device__ float g_posmax[Dd];                       // per-dim max of pos
__device__ float g_meanfeat[Zz * Cc];                // cluster-mean features
__device__ float g_kv[Zz * 2 * Cc];                  // [z][768]: key(384) | v(384)
__device__ float g_pmdot[Bn * Hh * Kk];              // pos-bias key term
__device__ float g_Q[(size_t)TOT * Cc];              // scaled Q
__device__ float g_O[(size_t)TOT * Cc];              // attention output (pre-proj)

// ---------------------------------------------------------------------------
// K0: per-dimension max of pos (values are positive uniforms)
// ---------------------------------------------------------------------------
__global__ void posmax_kernel(const float* __restrict__ pos) {
    __shared__ float s0[256];
    __shared__ float s1[256];
    int t = threadIdx.x;
    float m0 = -1e30f, m1 = -1e30f;
    const float2* p2 = (const float2*)pos;
    for (int i = t; i < TOT; i += 256) {
        float2 v = p2[i];
        m0 = fmaxf(m0, v.x);
        m1 = fmaxf(m1, v.y);
    }
    s0[t] = m0; s1[t] = m1;
    __syncthreads();
    for (int st = 128; st > 0; st >>= 1) {
        if (t < st) {
            s0[t] = fmaxf(s0[t], s0[t + st]);
            s1[t] = fmaxf(s1[t], s1[t + st]);
        }
        __syncthreads();
    }
    if (t == 0) { g_posmax[0] = s0[0]; g_posmax[1] = s1[0]; }
}

// ---------------------------------------------------------------------------
// K1: per-cluster mean of feat (gather over 32 members) + pos mean + pm_dot
//     pm_dot[b,h,k] = pos_mean . pos_w[h] + pos_b[h]
// ---------------------------------------------------------------------------
__global__ __launch_bounds__(128) void cluster_mean_kernel(
    const float* __restrict__ pos, const float* __restrict__ feat,
    const int* __restrict__ member_idx, const int* __restrict__ batch_idx,
    const float* __restrict__ pos_w, const float* __restrict__ pos_b)
{
    int z = blockIdx.x;
    int t = threadIdx.x;
    __shared__ int   idx[Mm];
    __shared__ int   bsh;
    __shared__ float pm[2];

    if (t < Mm) idx[t] = member_idx[z * Mm + t];
    if (t == 0) bsh = batch_idx[z * Mm];
    __syncthreads();
    int b = bsh;
    const float* fb = feat + (size_t)b * Nn * Cc;

    float a0 = 0.f, a1 = 0.f, a2 = 0.f;
    for (int m = 0; m < Mm; m++) {
        const float* fr = fb + (size_t)idx[m] * Cc;
        a0 += fr[t];
        a1 += fr[t + 128];
        a2 += fr[t + 256];
    }
    const float invM = 1.0f / (float)Mm;
    g_meanfeat[z * Cc + t]       = a0 * invM;
    g_meanfeat[z * Cc + t + 128] = a1 * invM;
    g_meanfeat[z * Cc + t + 256] = a2 * invM;

    if (t < Dd) {
        const float* pb = pos + (size_t)b * Nn * Dd;
        float s = 0.f;
        for (int m = 0; m < Mm; m++) s += pb[idx[m] * Dd + t];
        pm[t] = (s * invM) / g_posmax[t];
    }
    __syncthreads();
    if (t < Hh) {
        int kk = z & (Kk - 1);    // z % 256
        int bb = z >> 8;          // z / 256
        g_pmdot[(bb * Hh + t) * Kk + kk] =
            pm[0] * pos_w[t * Dd + 0] + pm[1] * pos_w[t * Dd + 1] + pos_b[t];
    }
}

// ---------------------------------------------------------------------------
// Tiled fp32 GEMM:  C[M][Nc] = alpha * (A[M][384] @ W[Nc][384]^T + bias[Nc])
// BM=BN=64, BK=32, 256 threads, 4x4 microtile. K fixed at 384.
// ---------------------------------------------------------------------------
__global__ __launch_bounds__(256) void gemm_bias_kernel(
    const float* __restrict__ A, const float* __restrict__ W,
    const float* __restrict__ bias, float* __restrict__ C,
    int M, int Nc, float alpha)
{
    __shared__ float As[32][68];   // [k][m], padded to keep 16B alignment
    __shared__ float Ws[32][68];   // [k][n]
    const int t  = threadIdx.x;
    const int m0 = blockIdx.y * 64;
    const int n0 = blockIdx.x * 64;
    const int tm = (t & 15) * 4;
    const int tn = (t >> 4) * 4;

    float acc[4][4] = {};

    for (int kt = 0; kt < 384; kt += 32) {
        #pragma unroll
        for (int i = 0; i < 2; i++) {
            int f   = t + i * 256;          // 0..511
            int row = f >> 3;               // 0..63
            int c0  = (f & 7) * 4;          // 0..28
            float4 va = *(const float4*)(A + (size_t)(m0 + row) * 384 + kt + c0);
            As[c0 + 0][row] = va.x; As[c0 + 1][row] = va.y;
            As[c0 + 2][row] = va.z; As[c0 + 3][row] = va.w;
            float4 vw = *(const float4*)(W + (size_t)(n0 + row) * 384 + kt + c0);
            Ws[c0 + 0][row] = vw.x; Ws[c0 + 1][row] = vw.y;
            Ws[c0 + 2][row] = vw.z; Ws[c0 + 3][row] = vw.w;
        }
        __syncthreads();
        #pragma unroll
        for (int kk = 0; kk < 32; kk++) {
            float4 a4 = *(const float4*)&As[kk][tm];
            float4 w4 = *(const float4*)&Ws[kk][tn];
            float a[4] = {a4.x, a4.y, a4.z, a4.w};
            float w[4] = {w4.x, w4.y, w4.z, w4.w};
            #pragma unroll
            for (int i = 0; i < 4; i++)
                #pragma unroll
                for (int j = 0; j < 4; j++)
                    acc[i][j] += a[i] * w[j];
        }
        __syncthreads();
    }

    #pragma unroll
    for (int j = 0; j < 4; j++) {
        float bj = bias[n0 + tn + j];
        #pragma unroll
        for (int i = 0; i < 4; i++)
            C[(size_t)(m0 + tm + i) * Nc + n0 + tn + j] = alpha * (acc[i][j] + bj);
    }
}

// ---------------------------------------------------------------------------
// K4: fused attention per (b, h, 128-query tile).
//   logits = Qs . K^T + pm_dot ; softmax over k (q-side bias term cancels);
//   O = P . V.  K/V/logits live in smem; 2 threads per query row.
// smem: K(8192) V(8192) S(128*257) pm(256) red(512) floats = 200192 bytes
// ---------------------------------------------------------------------------
#define ATTN_SMEM_FLOATS (8192 + 8192 + 128 * 257 + 256 + 512)
#define ATTN_SMEM_BYTES  (ATTN_SMEM_FLOATS * 4)

__global__ __launch_bounds__(256) void attn_kernel() {
    extern __shared__ float sm[];
    float* Ksm  = sm;                       // [256][32]
    float* Vsm  = sm + 8192;                // [256][32]
    float* Ssm  = sm + 16384;               // [128][257] (stride 257 => conflict-free)
    float* pmsm = Ssm + 128 * 257;          // [256]
    float* redM = pmsm + 256;               // [256] per-half max
    float* redS = redM + 256;               // [256] per-half sum

    const int t  = threadIdx.x;
    const int b  = blockIdx.z;
    const int h  = blockIdx.y;
    const int n0 = blockIdx.x * TQ;
    const int r    = t & 127;               // query row within tile
    const int half = t >> 7;                // 0/1: k-half (phase1/2), ch-half (phase3)

    // Load K and V tiles for this (b, h)
    const float* kvb = g_kv + (size_t)b * Kk * (2 * Cc);
    #pragma unroll
    for (int i = 0; i < 8; i++) {
        int f4 = t + i * 256;               // 2048 float4s
        int k  = f4 >> 3;
        int c0 = (f4 & 7) * 4;
        *(float4*)&Ksm[k * 32 + c0] =
            *(const float4*)&kvb[(size_t)k * (2 * Cc) + h * CHh + c0];
        *(float4*)&Vsm[k * 32 + c0] =
            *(const float4*)&kvb[(size_t)k * (2 * Cc) + Cc + h * CHh + c0];
    }
    pmsm[t] = g_pmdot[((size_t)b * Hh + h) * Kk + t];

    // Q row into registers (scale already folded in by the Q GEMM)
    const float* qrow = g_Q + ((size_t)b * Nn + n0 + r) * Cc + h * CHh;
    float qf[32];
    #pragma unroll
    for (int i = 0; i < 8; i++) {
        float4 v = *(const float4*)(qrow + i * 4);
        qf[i * 4 + 0] = v.x; qf[i * 4 + 1] = v.y;
        qf[i * 4 + 2] = v.z; qf[i * 4 + 3] = v.w;
    }
    __syncthreads();

    // Phase 1: logits for own k-half
    const int kbase = half * 128;
    for (int kk = 0; kk < 128; kk++) {
        int k = kbase + kk;
        const float4* kr = (const float4*)&Ksm[k * 32];
        float s0 = 0.f, s1 = 0.f, s2 = 0.f, s3 = 0.f;
        #pragma unroll
        for (int i = 0; i < 8; i++) {
            float4 kv4 = kr[i];
            s0 += qf[i * 4 + 0] * kv4.x;
            s1 += qf[i * 4 + 1] * kv4.y;
            s2 += qf[i * 4 + 2] * kv4.z;
            s3 += qf[i * 4 + 3] * kv4.w;
        }
        Ssm[r * 257 + k] = (s0 + s1) + (s2 + s3) + pmsm[k];
    }
    __syncthreads();

    // Phase 2: softmax (row split across 2 threads)
    float mx = -1e30f;
    for (int kk = 0; kk < 128; kk++)
        mx = fmaxf(mx, Ssm[r * 257 + kbase + kk]);
    redM[half * 128 + r] = mx;
    __syncthreads();
    float m = fmaxf(redM[r], redM[128 + r]);
    float sum = 0.f;
    for (int kk = 0; kk < 128; kk++) {
        int k = kbase + kk;
        float e = __expf(Ssm[r * 257 + k] - m);
        Ssm[r * 257 + k] = e;
        sum += e;
    }
    redS[half * 128 + r] = sum;
    __syncthreads();
    float inv = 1.0f / (redS[r] + redS[128 + r]);

    // Phase 3: O = P.V over own ch-half (16 channels)
    const int ch0 = half * 16;
    float acc[16] = {};
    for (int k = 0; k < Kk; k++) {
        float p = Ssm[r * 257 + k];
        const float4* vr = (const float4*)&Vsm[k * 32 + ch0];
        #pragma unroll
        for (int j = 0; j < 4; j++) {
            float4 v4 = vr[j];
            acc[4 * j + 0] += p * v4.x;
            acc[4 * j + 1] += p * v4.y;
            acc[4 * j + 2] += p * v4.z;
            acc[4 * j + 3] += p * v4.w;
        }
    }
    float* orow = g_O + ((size_t)b * Nn + n0 + r) * Cc + h * CHh + ch0;
    #pragma unroll
    for (int j = 0; j < 16; j++) orow[j] = acc[j] * inv;
}

// ---------------------------------------------------------------------------
// Launch
// ---------------------------------------------------------------------------
extern "C" void kernel_launch(void* const* d_in, const int* in_sizes, int n_in,
                              void* d_out, int out_size)
{
    const float* pos        = (const float*)d_in[0];
    const float* feat       = (const float*)d_in[1];
    const int*   member_idx = (const int*)  d_in[2];
    const int*   batch_idx  = (const int*)  d_in[3];
    const float* qkv_w      = (const float*)d_in[4];
    const float* qkv_b      = (const float*)d_in[5];
    const float* pos_w      = (const float*)d_in[6];
    const float* pos_b      = (const float*)d_in[7];
    const float* proj_w     = (const float*)d_in[8];
    const float* proj_b     = (const float*)d_in[9];
    (void)in_sizes; (void)n_in; (void)out_size;

    float *p_meanfeat, *p_kv, *p_Q, *p_O;
    cudaGetSymbolAddress((void**)&p_meanfeat, g_meanfeat);
    cudaGetSymbolAddress((void**)&p_kv,       g_kv);
    cudaGetSymbolAddress((void**)&p_Q,        g_Q);
    cudaGetSymbolAddress((void**)&p_O,        g_O);

    cudaFuncSetAttribute(attn_kernel,
                         cudaFuncAttributeMaxDynamicSharedMemorySize,
                         ATTN_SMEM_BYTES);

    // K0: pos max
    posmax_kernel<<<1, 256>>>(pos);

    // K1: cluster means + pm_dot
    cluster_mean_kernel<<<Zz, 128>>>(pos, feat, member_idx, batch_idx, pos_w, pos_b);

    // K2: kv_mean = mean_feat @ W_kv^T + b_kv  (rows 384..1151 of qkv_w)
    {
        dim3 grid((2 * Cc) / 64, Zz / 64);
        gemm_bias_kernel<<<grid, 256>>>(p_meanfeat, qkv_w + Cc * Cc, qkv_b + Cc,
                                        p_kv, Zz, 2 * Cc, 1.0f);
    }

    // K3: Qs = scale * (feat @ W_q^T + b_q)
    {
        dim3 grid(Cc / 64, TOT / 64);
        const float scale = 0.17677669529663687f;   // 32^{-1/2}
        gemm_bias_kernel<<<grid, 256>>>(feat, qkv_w, qkv_b, p_Q, TOT, Cc, scale);
    }

    // K4: fused attention
    attn_kernel<<<dim3(Nn / TQ, Hh, Bn), 256, ATTN_SMEM_BYTES>>>();

    // K5: out = O @ proj_w^T + proj_b
    {
        dim3 grid(Cc / 64, TOT / 64);
        gemm_bias_kernel<<<grid, 256>>>(p_O, proj_w, proj_b, (float*)d_out,
                                        TOT, Cc, 1.0f);
    }
}

// round 6
// speedup vs baseline: 1.2895x; 1.2895x over previous
#include <cuda_runtime.h>
#include <math.h>
#include <stdint.h>

// Problem constants
#define Bn   4
#define Nn   8192
#define Cc   384
#define Hh   12
#define Dd   2
#define Kk   256
#define Mm   32          // members per cluster
#define CHh  32          // channels per head
#define TOT  (Bn * Nn)   // 32768 rows
#define Zz   (Bn * Kk)   // 1024 clusters
#define TQ   128         // queries per attention CTA

typedef unsigned long long ull;

// ---------------------------------------------------------------------------
// packed f32x2 helpers (FFMA2 path — 2 fp32 FMA lanes per instruction)
// ---------------------------------------------------------------------------
__device__ __forceinline__ ull pack2(float x) {
    ull r;
    unsigned int xi = __float_as_uint(x);
    asm("mov.b64 %0, {%1, %1};" : "=l"(r) : "r"(xi));
    return r;
}
__device__ __forceinline__ void fma2(ull& d, ull a, ull b) {
    asm("fma.rn.f32x2 %0, %1, %2, %0;" : "+l"(d) : "l"(a), "l"(b));
}
__device__ __forceinline__ float2 unpack2(ull v) {
    unsigned int lo, hi;
    asm("mov.b64 {%0, %1}, %2;" : "=r"(lo), "=r"(hi) : "l"(v));
    float2 f;
    f.x = __uint_as_float(lo);
    f.y = __uint_as_float(hi);
    return f;
}

// ---------------------------------------------------------------------------
// Scratch (device globals: no allocation allowed in kernel_launch)
// ---------------------------------------------------------------------------
__device__ float g_posmax[Dd];
__device__ float g_meanfeat[Zz * Cc];
__device__ float g_kv[Zz * 2 * Cc];                  // [z][768]: key(384) | v(384)
__device__ float g_pmdot[Bn * Hh * Kk];
__device__ float g_Q[(size_t)TOT * Cc];              // scaled Q
__device__ float g_O[(size_t)TOT * Cc];              // attention output (pre-proj)

// ---------------------------------------------------------------------------
// K0: per-dimension max of pos
// ---------------------------------------------------------------------------
__global__ void posmax_kernel(const float* __restrict__ pos) {
    __shared__ float s0[256];
    __shared__ float s1[256];
    int t = threadIdx.x;
    float m0 = -1e30f, m1 = -1e30f;
    const float2* p2 = (const float2*)pos;
    for (int i = t; i < TOT; i += 256) {
        float2 v = p2[i];
        m0 = fmaxf(m0, v.x);
        m1 = fmaxf(m1, v.y);
    }
    s0[t] = m0; s1[t] = m1;
    __syncthreads();
    for (int st = 128; st > 0; st >>= 1) {
        if (t < st) {
            s0[t] = fmaxf(s0[t], s0[t + st]);
            s1[t] = fmaxf(s1[t], s1[t + st]);
        }
        __syncthreads();
    }
    if (t == 0) { g_posmax[0] = s0[0]; g_posmax[1] = s1[0]; }
}

// ---------------------------------------------------------------------------
// K1: per-cluster mean of feat + pos mean + pm_dot
// ---------------------------------------------------------------------------
__global__ __launch_bounds__(128) void cluster_mean_kernel(
    const float* __restrict__ pos, const float* __restrict__ feat,
    const int* __restrict__ member_idx, const int* __restrict__ batch_idx,
    const float* __restrict__ pos_w, const float* __restrict__ pos_b)
{
    int z = blockIdx.x;
    int t = threadIdx.x;
    __shared__ int   idx[Mm];
    __shared__ int   bsh;
    __shared__ float pm[2];

    if (t < Mm) idx[t] = member_idx[z * Mm + t];
    if (t == 0) bsh = batch_idx[z * Mm];
    __syncthreads();
    int b = bsh;
    const float* fb = feat + (size_t)b * Nn * Cc;

    float a0 = 0.f, a1 = 0.f, a2 = 0.f;
    for (int m = 0; m < Mm; m++) {
        const float* fr = fb + (size_t)idx[m] * Cc;
        a0 += fr[t];
        a1 += fr[t + 128];
        a2 += fr[t + 256];
    }
    const float invM = 1.0f / (float)Mm;
    g_meanfeat[z * Cc + t]       = a0 * invM;
    g_meanfeat[z * Cc + t + 128] = a1 * invM;
    g_meanfeat[z * Cc + t + 256] = a2 * invM;

    if (t < Dd) {
        const float* pb = pos + (size_t)b * Nn * Dd;
        float s = 0.f;
        for (int m = 0; m < Mm; m++) s += pb[idx[m] * Dd + t];
        pm[t] = (s * invM) / g_posmax[t];
    }
    __syncthreads();
    if (t < Hh) {
        int kk = z & (Kk - 1);
        int bb = z >> 8;
        g_pmdot[(bb * Hh + t) * Kk + kk] =
            pm[0] * pos_w[t * Dd + 0] + pm[1] * pos_w[t * Dd + 1] + pos_b[t];
    }
}

// ---------------------------------------------------------------------------
// K2/K3/K5: fp32x2 GEMM  C[M][Nc] = alpha*(A[M][384] @ W[Nc][384]^T + bias)
// 128x128 tile, BK=16, 256 threads, 8x8 microtile (split 4+4 at +64),
// f32x2 packed accumulators.
// ---------------------------------------------------------------------------
__global__ __launch_bounds__(256) void gemm128_kernel(
    const float* __restrict__ A, const float* __restrict__ W,
    const float* __restrict__ bias, float* __restrict__ C,
    int Nc, float alpha)
{
    __shared__ float As[16][136];
    __shared__ float Ws[16][136];
    const int t  = threadIdx.x;
    const int m0 = blockIdx.y * 128;
    const int n0 = blockIdx.x * 128;
    const int tm = (t & 15) * 4;     // rows tm..tm+3, tm+64..tm+67
    const int tn = (t >> 4) * 4;     // cols tn..tn+3, tn+64..tn+67

    ull acc[8][4] = {};

    for (int kt = 0; kt < 384; kt += 16) {
        #pragma unroll
        for (int i = 0; i < 2; i++) {
            int f   = t + i * 256;          // 0..511
            int row = f >> 2;               // 0..127
            int c0  = (f & 3) * 4;          // 0,4,8,12
            float4 va = *(const float4*)(A + (size_t)(m0 + row) * 384 + kt + c0);
            As[c0 + 0][row] = va.x; As[c0 + 1][row] = va.y;
            As[c0 + 2][row] = va.z; As[c0 + 3][row] = va.w;
            float4 vw = *(const float4*)(W + (size_t)(n0 + row) * 384 + kt + c0);
            Ws[c0 + 0][row] = vw.x; Ws[c0 + 1][row] = vw.y;
            Ws[c0 + 2][row] = vw.z; Ws[c0 + 3][row] = vw.w;
        }
        __syncthreads();
        #pragma unroll
        for (int kk = 0; kk < 16; kk++) {
            float4 a0 = *(const float4*)&As[kk][tm];
            float4 a1 = *(const float4*)&As[kk][tm + 64];
            ulonglong2 w0 = *(const ulonglong2*)&Ws[kk][tn];
            ulonglong2 w1 = *(const ulonglong2*)&Ws[kk][tn + 64];
            ull aa[8];
            aa[0] = pack2(a0.x); aa[1] = pack2(a0.y);
            aa[2] = pack2(a0.z); aa[3] = pack2(a0.w);
            aa[4] = pack2(a1.x); aa[5] = pack2(a1.y);
            aa[6] = pack2(a1.z); aa[7] = pack2(a1.w);
            ull wv[4] = {w0.x, w0.y, w1.x, w1.y};
            #pragma unroll
            for (int i = 0; i < 8; i++)
                #pragma unroll
                for (int jp = 0; jp < 4; jp++)
                    fma2(acc[i][jp], aa[i], wv[jp]);
        }
        __syncthreads();
    }

    #pragma unroll
    for (int i = 0; i < 8; i++) {
        int r = m0 + tm + (i & 3) + (i >> 2) * 64;
        #pragma unroll
        for (int jp = 0; jp < 4; jp++) {
            int kc = n0 + tn + (jp & 1) * 2 + (jp >> 1) * 64;
            float2 v = unpack2(acc[i][jp]);
            float2 o;
            o.x = alpha * (v.x + bias[kc + 0]);
            o.y = alpha * (v.y + bias[kc + 1]);
            *(float2*)(C + (size_t)r * Nc + kc) = o;
        }
    }
}

// ---------------------------------------------------------------------------
// K4: fused attention per (b, h, 128-query tile). 512 threads.
//  Phase 1: St[k][r] = Q.K^T + pm   (8x8 f32x2 microtile GEMM)
//  Phase 2: softmax over k (4 threads/row), q-side bias term cancels
//  Phase 3: O = P.V  (4x4 f32x2 microtile, k split in 2 halves)
// ---------------------------------------------------------------------------
#define SM_Q    0                       // [32][132]
#define SM_K    (32 * 132)              // [32][260]
#define SM_V    (SM_K + 32 * 260)       // [256][32]
#define SM_S    (SM_V + 256 * 32)       // [256][132]  St[k][r]
#define SM_PM   (SM_S + 256 * 132)      // [256]
#define SM_RM   (SM_PM + 256)           // [4][128]
#define SM_RS   (SM_RM + 512)           // [4][128]
#define SM_INV  (SM_RS + 512)           // [128]
#define ATTN_SMEM_FLOATS (SM_INV + 128)
#define ATTN_SMEM_BYTES  (ATTN_SMEM_FLOATS * 4)

__global__ __launch_bounds__(512, 1) void attn_kernel() {
    extern __shared__ float sm[];
    float* Qs   = sm + SM_Q;
    float* Ks   = sm + SM_K;
    float* Vs   = sm + SM_V;
    float* St   = sm + SM_S;
    float* pm   = sm + SM_PM;
    float* redM = sm + SM_RM;
    float* redS = sm + SM_RS;
    float* invS = sm + SM_INV;

    const int t  = threadIdx.x;
    const int b  = blockIdx.z;
    const int h  = blockIdx.y;
    const int n0 = blockIdx.x * TQ;

    // ---- load Q (transposed), K (transposed), V (row-major) ----
    #pragma unroll
    for (int i = 0; i < 2; i++) {
        int f  = t + i * 512;            // 0..1023
        int r  = f >> 3;
        int c0 = (f & 7) * 4;
        float4 v = *(const float4*)(g_Q + ((size_t)b * Nn + n0 + r) * Cc + h * CHh + c0);
        Qs[(c0 + 0) * 132 + r] = v.x; Qs[(c0 + 1) * 132 + r] = v.y;
        Qs[(c0 + 2) * 132 + r] = v.z; Qs[(c0 + 3) * 132 + r] = v.w;
    }
    const float* kvb = g_kv + (size_t)b * Kk * (2 * Cc);
    #pragma unroll
    for (int i = 0; i < 4; i++) {
        int f  = t + i * 512;            // 0..2047
        int k  = f >> 3;
        int c0 = (f & 7) * 4;
        float4 kv4 = *(const float4*)&kvb[(size_t)k * (2 * Cc) + h * CHh + c0];
        Ks[(c0 + 0) * 260 + k] = kv4.x; Ks[(c0 + 1) * 260 + k] = kv4.y;
        Ks[(c0 + 2) * 260 + k] = kv4.z; Ks[(c0 + 3) * 260 + k] = kv4.w;
        float4 vv = *(const float4*)&kvb[(size_t)k * (2 * Cc) + Cc + h * CHh + c0];
        *(float4*)&Vs[k * 32 + c0] = vv;
    }
    if (t < 256) pm[t] = g_pmdot[((size_t)b * Hh + h) * Kk + t];
    __syncthreads();

    // ---- Phase 1: S = Q.K^T + pm, stored transposed St[k][r] ----
    {
        const int tm = (t & 15) * 4;     // q rows (+64)
        const int tk = (t >> 4) * 4;     // k cols (+128)
        ull acc[8][4] = {};
        #pragma unroll 8
        for (int c = 0; c < 32; c++) {
            float4 q0 = *(const float4*)&Qs[c * 132 + tm];
            float4 q1 = *(const float4*)&Qs[c * 132 + tm + 64];
            ulonglong2 k0 = *(const ulonglong2*)&Ks[c * 260 + tk];
            ulonglong2 k1 = *(const ulonglong2*)&Ks[c * 260 + tk + 128];
            ull aa[8];
            aa[0] = pack2(q0.x); aa[1] = pack2(q0.y);
            aa[2] = pack2(q0.z); aa[3] = pack2(q0.w);
            aa[4] = pack2(q1.x); aa[5] = pack2(q1.y);
            aa[6] = pack2(q1.z); aa[7] = pack2(q1.w);
            ull kv[4] = {k0.x, k0.y, k1.x, k1.y};
            #pragma unroll
            for (int i = 0; i < 8; i++)
                #pragma unroll
                for (int jp = 0; jp < 4; jp++)
                    fma2(acc[i][jp], aa[i], kv[jp]);
        }
        #pragma unroll
        for (int i = 0; i < 8; i++) {
            int r = tm + (i & 3) + (i >> 2) * 64;
            #pragma unroll
            for (int jp = 0; jp < 4; jp++) {
                int kc = tk + (jp & 1) * 2 + (jp >> 1) * 128;
                float2 v = unpack2(acc[i][jp]);
                St[(kc + 0) * 132 + r] = v.x + pm[kc + 0];
                St[(kc + 1) * 132 + r] = v.y + pm[kc + 1];
            }
        }
    }
    __syncthreads();

    // ---- Phase 2: softmax per row (4 threads/row) ----
    {
        const int r   = t & 127;
        const int seg = t >> 7;          // 0..3
        const int kb  = seg * 64;
        float mx = -1e30f;
        for (int kk = 0; kk < 64; kk++)
            mx = fmaxf(mx, St[(kb + kk) * 132 + r]);
        redM[seg * 128 + r] = mx;
        __syncthreads();
        float m = fmaxf(fmaxf(redM[r], redM[128 + r]),
                        fmaxf(redM[256 + r], redM[384 + r]));
        float s = 0.f;
        for (int kk = 0; kk < 64; kk++) {
            int k = kb + kk;
            float e = __expf(St[k * 132 + r] - m);
            St[k * 132 + r] = e;
            s += e;
        }
        redS[seg * 128 + r] = s;
        __syncthreads();
        if (seg == 0)
            invS[r] = 1.0f / (redS[r] + redS[128 + r] + redS[256 + r] + redS[384 + r]);
    }
    __syncthreads();

    // ---- Phase 3: O = P.V (4 rows x 4 cols per thread, k split in halves) ----
    {
        const int kh = t >> 8;                 // 0/1 k-half
        const int r0 = (t & 31) * 4;           // 4 query rows
        const int c0 = ((t >> 5) & 7) * 4;     // 4 channels
        ull acc[4][2] = {};
        const int kbase = kh * 128;
        #pragma unroll 8
        for (int kk = 0; kk < 128; kk++) {
            int k = kbase + kk;
            float4 p  = *(const float4*)&St[k * 132 + r0];
            ulonglong2 v2 = *(const ulonglong2*)&Vs[k * 32 + c0];
            ull pp[4];
            pp[0] = pack2(p.x); pp[1] = pack2(p.y);
            pp[2] = pack2(p.z); pp[3] = pack2(p.w);
            #pragma unroll
            for (int i = 0; i < 4; i++) {
                fma2(acc[i][0], pp[i], v2.x);
                fma2(acc[i][1], pp[i], v2.y);
            }
        }
        // combine halves via scratch (reuse Qs region: 4096 floats needed)
        float* scratch = Qs;
        int slot = (t & 255) * 16;
        if (kh == 1) {
            #pragma unroll
            for (int i = 0; i < 4; i++) {
                float2 v0 = unpack2(acc[i][0]);
                float2 v1 = unpack2(acc[i][1]);
                scratch[slot + i * 4 + 0] = v0.x;
                scratch[slot + i * 4 + 1] = v0.y;
                scratch[slot + i * 4 + 2] = v1.x;
                scratch[slot + i * 4 + 3] = v1.y;
            }
        }
        __syncthreads();
        if (kh == 0) {
            #pragma unroll
            for (int i = 0; i < 4; i++) {
                float inv = invS[r0 + i];
                float2 v0 = unpack2(acc[i][0]);
                float2 v1 = unpack2(acc[i][1]);
                float4 o;
                o.x = (v0.x + scratch[slot + i * 4 + 0]) * inv;
                o.y = (v0.y + scratch[slot + i * 4 + 1]) * inv;
                o.z = (v1.x + scratch[slot + i * 4 + 2]) * inv;
                o.w = (v1.y + scratch[slot + i * 4 + 3]) * inv;
                *(float4*)(g_O + ((size_t)b * Nn + n0 + r0 + i) * Cc + h * CHh + c0) = o;
            }
        }
    }
}

// ---------------------------------------------------------------------------
// Launch
// ---------------------------------------------------------------------------
extern "C" void kernel_launch(void* const* d_in, const int* in_sizes, int n_in,
                              void* d_out, int out_size)
{
    const float* pos        = (const float*)d_in[0];
    const float* feat       = (const float*)d_in[1];
    const int*   member_idx = (const int*)  d_in[2];
    const int*   batch_idx  = (const int*)  d_in[3];
    const float* qkv_w      = (const float*)d_in[4];
    const float* qkv_b      = (const float*)d_in[5];
    const float* pos_w      = (const float*)d_in[6];
    const float* pos_b      = (const float*)d_in[7];
    const float* proj_w     = (const float*)d_in[8];
    const float* proj_b     = (const float*)d_in[9];
    (void)in_sizes; (void)n_in; (void)out_size;

    float *p_meanfeat, *p_kv, *p_Q, *p_O;
    cudaGetSymbolAddress((void**)&p_meanfeat, g_meanfeat);
    cudaGetSymbolAddress((void**)&p_kv,       g_kv);
    cudaGetSymbolAddress((void**)&p_Q,        g_Q);
    cudaGetSymbolAddress((void**)&p_O,        g_O);

    cudaFuncSetAttribute(attn_kernel,
                         cudaFuncAttributeMaxDynamicSharedMemorySize,
                         ATTN_SMEM_BYTES);

    // K0: pos max
    posmax_kernel<<<1, 256>>>(pos);

    // K1: cluster means + pm_dot
    cluster_mean_kernel<<<Zz, 128>>>(pos, feat, member_idx, batch_idx, pos_w, pos_b);

    // K2: kv_mean = mean_feat @ W_kv^T + b_kv  (rows 384..1151 of qkv_w)
    {
        dim3 grid((2 * Cc) / 128, Zz / 128);
        gemm128_kernel<<<grid, 256>>>(p_meanfeat, qkv_w + Cc * Cc, qkv_b + Cc,
                                      p_kv, 2 * Cc, 1.0f);
    }

    // K3: Qs = scale * (feat @ W_q^T + b_q)
    {
        dim3 grid(Cc / 128, TOT / 128);
        const float scale = 0.17677669529663687f;   // 32^{-1/2}
        gemm128_kernel<<<grid, 256>>>(feat, qkv_w, qkv_b, p_Q, Cc, scale);
    }

    // K4: fused attention
    attn_kernel<<<dim3(Nn / TQ, Hh, Bn), 512, ATTN_SMEM_BYTES>>>();

    // K5: out = O @ proj_w^T + proj_b
    {
        dim3 grid(Cc / 128, TOT / 128);
        gemm128_kernel<<<grid, 256>>>(p_O, proj_w, proj_b, (float*)d_out,
                                      Cc, 1.0f);
    }
}